// round 2
// baseline (speedup 1.0000x reference)
#include <cuda_runtime.h>

// Householder reflection per row:
//   out[b,:] = z[b,:] - 2 * v[b,:] * (v[b]·z[b]) / (v[b]·v[b])
// B = 8192 rows, L = 4096 cols, fp32.
//
// Persistent CTAs, software-pipelined across rows: issue next row's loads
// before reducing the current row so LDGs stay in flight through the
// shfl/barrier phase. Streaming hints (ldcs/stcs) — no line is ever reused.

constexpr int THREADS = 256;
constexpr int L4 = 4096 / 4;              // float4s per row
constexpr int PER = L4 / THREADS;         // 4 float4 per thread
constexpr int GRID = 152 * 8;             // persistent grid (GB300: 152 SMs, occ 8)

struct RowBuf {
    float4 rv[PER];
    float4 rz[PER];
};

__device__ __forceinline__ void load_row(const float4* __restrict__ v,
                                         const float4* __restrict__ z,
                                         size_t base, RowBuf& b)
{
    #pragma unroll
    for (int i = 0; i < PER; i++)
        b.rv[i] = __ldcs(v + base + threadIdx.x + i * THREADS);
    #pragma unroll
    for (int i = 0; i < PER; i++)
        b.rz[i] = __ldcs(z + base + threadIdx.x + i * THREADS);
}

__device__ __forceinline__ void process_row(const RowBuf& b,
                                            float4* __restrict__ out,
                                            size_t base,
                                            float* s_vz, float* s_vv, float* s_scale)
{
    float dvz = 0.0f, dvv = 0.0f;
    #pragma unroll
    for (int i = 0; i < PER; i++) {
        dvz += b.rv[i].x * b.rz[i].x + b.rv[i].y * b.rz[i].y
             + b.rv[i].z * b.rz[i].z + b.rv[i].w * b.rz[i].w;
        dvv += b.rv[i].x * b.rv[i].x + b.rv[i].y * b.rv[i].y
             + b.rv[i].z * b.rv[i].z + b.rv[i].w * b.rv[i].w;
    }

    #pragma unroll
    for (int off = 16; off > 0; off >>= 1) {
        dvz += __shfl_xor_sync(0xFFFFFFFFu, dvz, off);
        dvv += __shfl_xor_sync(0xFFFFFFFFu, dvv, off);
    }

    const int lane = threadIdx.x & 31;
    const int wid  = threadIdx.x >> 5;
    if (lane == 0) { s_vz[wid] = dvz; s_vv[wid] = dvv; }
    __syncthreads();

    if (wid == 0) {
        float a = (lane < 8) ? s_vz[lane] : 0.0f;
        float c = (lane < 8) ? s_vv[lane] : 0.0f;
        #pragma unroll
        for (int off = 4; off > 0; off >>= 1) {
            a += __shfl_xor_sync(0xFFFFFFFFu, a, off);
            c += __shfl_xor_sync(0xFFFFFFFFu, c, off);
        }
        if (lane == 0) *s_scale = 2.0f * a / c;
    }
    __syncthreads();

    const float scale = *s_scale;

    #pragma unroll
    for (int i = 0; i < PER; i++) {
        float4 o;
        o.x = b.rz[i].x - scale * b.rv[i].x;
        o.y = b.rz[i].y - scale * b.rv[i].y;
        o.z = b.rz[i].z - scale * b.rv[i].z;
        o.w = b.rz[i].w - scale * b.rv[i].w;
        __stcs(out + base + threadIdx.x + i * THREADS, o);
    }
}

__global__ __launch_bounds__(THREADS, 8)
void householder_pipe_kernel(const float4* __restrict__ v,
                             const float4* __restrict__ z,
                             float4* __restrict__ out,
                             int B)
{
    __shared__ float s_vz[8];
    __shared__ float s_vv[8];
    __shared__ float s_scale;

    int row = blockIdx.x;
    if (row >= B) return;

    RowBuf bufA, bufB;
    load_row(v, z, (size_t)row * L4, bufA);

    // 2x-unrolled ping-pong so buffers stay in registers
    while (true) {
        // --- A resident, prefetch into B ---
        int next = row + GRID;
        if (next < B) load_row(v, z, (size_t)next * L4, bufB);
        process_row(bufA, out, (size_t)row * L4, s_vz, s_vv, &s_scale);
        if (next >= B) break;
        row = next;

        // --- B resident, prefetch into A ---
        next = row + GRID;
        if (next < B) load_row(v, z, (size_t)next * L4, bufA);
        process_row(bufB, out, (size_t)row * L4, s_vz, s_vv, &s_scale);
        if (next >= B) break;
        row = next;
    }
}

extern "C" void kernel_launch(void* const* d_in, const int* in_sizes, int n_in,
                              void* d_out, int out_size)
{
    const float4* v = (const float4*)d_in[0];
    const float4* z = (const float4*)d_in[1];
    float4* out = (float4*)d_out;

    const int B = in_sizes[0] / 4096;   // 8192
    const int grid = (B < GRID) ? B : GRID;
    householder_pipe_kernel<<<grid, THREADS>>>(v, z, out, B);
}

// round 4
// speedup vs baseline: 2.0333x; 2.0333x over previous
#include <cuda_runtime.h>
#include <cstdint>

// Householder reflection per row, B=8192, L=4096, fp32.
//   out[b,:] = z[b,:] - 2 * v[b,:] * (v.z)/(v.v)
//
// Persistent CTA per SM with cp.async.cg pipeline into smem:
// 6 stages x 32KB (one row of v + z per stage), 5 rows of loads always in
// flight via the async copy engine -> memory system never drains during the
// per-row reduction/barriers. Each thread's cp.async slice is private to that
// thread, so wait_group ordering alone covers data readiness and reuse.

constexpr int THREADS = 512;
constexpr int L      = 4096;
constexpr int L4     = L / 4;           // 1024 float4 per row
constexpr int PER    = L4 / THREADS;    // 2 float4 per thread per tensor
constexpr int STAGES = 6;
constexpr int STAGE_F4 = 2 * L4;        // v + z, 2048 float4 = 32KB
constexpr size_t SMEM_BYTES = (size_t)STAGES * STAGE_F4 * sizeof(float4);
constexpr int GRID_MAX = 152;           // GB300: 152 SMs

__device__ __forceinline__ uint32_t smem_u32(const void* p) {
    return (uint32_t)__cvta_generic_to_shared(p);
}

__global__ __launch_bounds__(THREADS, 1)
void hh_pipe_kernel(const float4* __restrict__ v,
                    const float4* __restrict__ z,
                    float4* __restrict__ out,
                    int B)
{
    extern __shared__ float4 sm[];       // [STAGES][2048]: v 0..1023, z 1024..2047
    __shared__ float s_part[32];         // 16 warps x {vz, vv}
    __shared__ float s_scale;

    const int t    = threadIdx.x;
    const int bid  = blockIdx.x;
    const int grid = gridDim.x;
    const int lane = t & 31;
    const int wid  = t >> 5;

    auto issue_stage = [&](int s, int row) {
        if (row < B) {
            const float4* vg = v + (size_t)row * L4;
            const float4* zg = z + (size_t)row * L4;
            float4* vs = sm + (size_t)s * STAGE_F4;
            float4* zs = vs + L4;
            #pragma unroll
            for (int i = 0; i < PER; i++) {
                uint32_t a = smem_u32(vs + t + i * THREADS);
                asm volatile("cp.async.cg.shared.global [%0], [%1], 16;\n"
                             :: "r"(a), "l"(vg + t + i * THREADS));
            }
            #pragma unroll
            for (int i = 0; i < PER; i++) {
                uint32_t a = smem_u32(zs + t + i * THREADS);
                asm volatile("cp.async.cg.shared.global [%0], [%1], 16;\n"
                             :: "r"(a), "l"(zg + t + i * THREADS));
            }
        }
        asm volatile("cp.async.commit_group;\n");
    };

    // Prologue: fill STAGES-1 stages
    #pragma unroll
    for (int s = 0; s < STAGES - 1; s++)
        issue_stage(s, bid + s * grid);

    const int nrows = (bid < B) ? (B - bid + grid - 1) / grid : 0;

    for (int i = 0; i < nrows; i++) {
        // Oldest group (row i) complete for this thread's slice
        asm volatile("cp.async.wait_group %0;\n" :: "n"(STAGES - 2));

        // Immediately refill the freed stage (consumed at iter i-1)
        issue_stage((i + STAGES - 1) % STAGES, bid + (i + STAGES - 1) * grid);

        const int s = i % STAGES;
        const float4* vs = sm + (size_t)s * STAGE_F4;
        const float4* zs = vs + L4;

        // Load own slice into registers (single smem pass per row)
        float4 rv[PER], rz[PER];
        #pragma unroll
        for (int k = 0; k < PER; k++) rv[k] = vs[t + k * THREADS];
        #pragma unroll
        for (int k = 0; k < PER; k++) rz[k] = zs[t + k * THREADS];

        float dvz = 0.0f, dvv = 0.0f;
        #pragma unroll
        for (int k = 0; k < PER; k++) {
            dvz += rv[k].x * rz[k].x + rv[k].y * rz[k].y
                 + rv[k].z * rz[k].z + rv[k].w * rz[k].w;
            dvv += rv[k].x * rv[k].x + rv[k].y * rv[k].y
                 + rv[k].z * rv[k].z + rv[k].w * rv[k].w;
        }

        #pragma unroll
        for (int off = 16; off > 0; off >>= 1) {
            dvz += __shfl_xor_sync(0xFFFFFFFFu, dvz, off);
            dvv += __shfl_xor_sync(0xFFFFFFFFu, dvv, off);
        }
        if (lane == 0) { s_part[wid] = dvz; s_part[16 + wid] = dvv; }
        __syncthreads();

        if (wid == 0) {
            float a = (lane < 16) ? s_part[lane] : 0.0f;
            float c = (lane < 16) ? s_part[16 + lane] : 0.0f;
            #pragma unroll
            for (int off = 8; off > 0; off >>= 1) {
                a += __shfl_xor_sync(0xFFFFFFFFu, a, off);
                c += __shfl_xor_sync(0xFFFFFFFFu, c, off);
            }
            if (lane == 0) s_scale = 2.0f * a / c;
        }
        __syncthreads();

        const float scale = s_scale;
        const int row = bid + i * grid;
        float4* og = out + (size_t)row * L4;

        #pragma unroll
        for (int k = 0; k < PER; k++) {
            float4 o;
            o.x = rz[k].x - scale * rv[k].x;
            o.y = rz[k].y - scale * rv[k].y;
            o.z = rz[k].z - scale * rv[k].z;
            o.w = rz[k].w - scale * rv[k].w;
            __stcs(og + t + k * THREADS, o);
        }
    }
}

extern "C" void kernel_launch(void* const* d_in, const int* in_sizes, int n_in,
                              void* d_out, int out_size)
{
    const float4* v = (const float4*)d_in[0];
    const float4* z = (const float4*)d_in[1];
    float4* out = (float4*)d_out;

    const int B = in_sizes[0] / L;       // 8192

    cudaFuncSetAttribute(hh_pipe_kernel,
                         cudaFuncAttributeMaxDynamicSharedMemorySize,
                         (int)SMEM_BYTES);

    const int grid = (B < GRID_MAX) ? B : GRID_MAX;
    hh_pipe_kernel<<<grid, THREADS, SMEM_BYTES>>>(v, z, out, B);
}

// round 5
// speedup vs baseline: 2.5038x; 1.2314x over previous
#include <cuda_runtime.h>
#include <cstdint>

// Householder reflection per row, B=8192, L=4096, fp32.
//   out[b,:] = z[b,:] - 2 * v[b,:] * (v.z)/(v.v)
//
// One CTA per row (grid=8192, 256 threads). Loads go through cp.async.bulk
// (TMA/UBLKCP) into smem instead of per-thread LDG — this bypasses the
// per-SM L1tex wavefront queue whose cross-CTA contention causes the ~2x
// completion spread documented for front-batched-LDG rmsnorm-shaped kernels.
// ~6 CTAs/SM co-resident: TMA streams some rows while others reduce/store.

constexpr int THREADS = 256;
constexpr int L       = 4096;
constexpr int L4      = L / 4;            // 1024 float4 per row
constexpr int PER     = L4 / THREADS;     // 4 float4 per thread per tensor
constexpr int ROW_BYTES   = L * 4;        // 16384
constexpr int STAGE_BYTES = 2 * ROW_BYTES; // 32768 (v + z)

__device__ __forceinline__ uint32_t smem_u32(const void* p) {
    return (uint32_t)__cvta_generic_to_shared(p);
}

__global__ __launch_bounds__(THREADS)
void hh_tma_kernel(const float4* __restrict__ v,
                   const float4* __restrict__ z,
                   float4* __restrict__ out)
{
    extern __shared__ float4 sm[];            // v: [0,1024), z: [1024,2048)
    __shared__ __align__(8) unsigned long long mbar;
    __shared__ float s_part[16];              // 8 warps x {vz, vv}
    __shared__ float s_scale;

    const int t    = threadIdx.x;
    const int lane = t & 31;
    const int wid  = t >> 5;
    const size_t base = (size_t)blockIdx.x * L4;

    const uint32_t mb = smem_u32(&mbar);

    if (t == 0) {
        asm volatile("mbarrier.init.shared::cta.b64 [%0], %1;"
                     :: "r"(mb), "r"(1));
        asm volatile("fence.proxy.async.shared::cta;" ::: "memory");
    }
    __syncthreads();

    if (t == 0) {
        asm volatile("mbarrier.arrive.expect_tx.shared::cta.b64 _, [%0], %1;"
                     :: "r"(mb), "r"(STAGE_BYTES) : "memory");
        asm volatile("cp.async.bulk.shared::cta.global.mbarrier::complete_tx::bytes"
                     " [%0], [%1], %2, [%3];"
                     :: "r"(smem_u32(sm)), "l"(v + base), "r"(ROW_BYTES), "r"(mb)
                     : "memory");
        asm volatile("cp.async.bulk.shared::cta.global.mbarrier::complete_tx::bytes"
                     " [%0], [%1], %2, [%3];"
                     :: "r"(smem_u32(sm + L4)), "l"(z + base), "r"(ROW_BYTES), "r"(mb)
                     : "memory");
    }

    // Wait (parity 0, single-shot barrier), acquire for generic smem reads
    {
        uint32_t done;
        asm volatile(
            "{\n\t.reg .pred p;\n\t"
            "mbarrier.try_wait.parity.acquire.cta.shared::cta.b64 p, [%1], %2;\n\t"
            "selp.b32 %0, 1, 0, p;\n\t}"
            : "=r"(done) : "r"(mb), "r"(0) : "memory");
        while (!done) {
            asm volatile(
                "{\n\t.reg .pred p;\n\t"
                "mbarrier.try_wait.parity.acquire.cta.shared::cta.b64 p, [%1], %2, 0x989680;\n\t"
                "selp.b32 %0, 1, 0, p;\n\t}"
                : "=r"(done) : "r"(mb), "r"(0) : "memory");
        }
    }

    // Dot pass from smem
    float dvz = 0.0f, dvv = 0.0f;
    #pragma unroll
    for (int i = 0; i < PER; i++) {
        const float4 a = sm[t + i * THREADS];
        const float4 b = sm[L4 + t + i * THREADS];
        dvz += a.x * b.x + a.y * b.y + a.z * b.z + a.w * b.w;
        dvv += a.x * a.x + a.y * a.y + a.z * a.z + a.w * a.w;
    }

    #pragma unroll
    for (int off = 16; off > 0; off >>= 1) {
        dvz += __shfl_xor_sync(0xFFFFFFFFu, dvz, off);
        dvv += __shfl_xor_sync(0xFFFFFFFFu, dvv, off);
    }
    if (lane == 0) { s_part[wid] = dvz; s_part[8 + wid] = dvv; }
    __syncthreads();

    if (wid == 0) {
        float a = (lane < 8) ? s_part[lane] : 0.0f;
        float c = (lane < 8) ? s_part[8 + lane] : 0.0f;
        #pragma unroll
        for (int off = 4; off > 0; off >>= 1) {
            a += __shfl_xor_sync(0xFFFFFFFFu, a, off);
            c += __shfl_xor_sync(0xFFFFFFFFu, c, off);
        }
        if (lane == 0) s_scale = 2.0f * a / c;
    }
    __syncthreads();

    const float scale = s_scale;
    float4* og = out + base;

    // Output pass: re-read smem (cheap LDS), streaming stores
    #pragma unroll
    for (int i = 0; i < PER; i++) {
        const float4 a = sm[t + i * THREADS];
        const float4 b = sm[L4 + t + i * THREADS];
        float4 o;
        o.x = b.x - scale * a.x;
        o.y = b.y - scale * a.y;
        o.z = b.z - scale * a.z;
        o.w = b.w - scale * a.w;
        __stcs(og + t + i * THREADS, o);
    }
}

extern "C" void kernel_launch(void* const* d_in, const int* in_sizes, int n_in,
                              void* d_out, int out_size)
{
    const float4* v = (const float4*)d_in[0];
    const float4* z = (const float4*)d_in[1];
    float4* out = (float4*)d_out;

    const int B = in_sizes[0] / L;    // 8192

    static bool attr_set = false;
    if (!attr_set) {
        cudaFuncSetAttribute(hh_tma_kernel,
                             cudaFuncAttributeMaxDynamicSharedMemorySize,
                             STAGE_BYTES);
        attr_set = true;
    }

    hh_tma_kernel<<<B, THREADS, STAGE_BYTES>>>(v, z, out);
}